// round 3
// baseline (speedup 1.0000x reference)
#include <cuda_runtime.h>
#include <math.h>

#define NMAX 100000
#define EMAX 1600000

// Scratch (device globals — no allocation allowed in kernel_launch)
__device__ __align__(16) float g_deg[NMAX];
__device__ __align__(16) float g_dinv[NMAX];
__device__ __align__(16) float g_aggx[NMAX * 2];
__device__ __align__(16) float g_h2pre[NMAX * 32];
__device__ __align__(16) float g_agg2[NMAX * 32];
__device__ __align__(16) float g_na[NMAX * 16];
__device__ __align__(16) float g_nb[NMAX * 16];
__device__ int g_i64;   // 1 if edge_index is int64, 0 if int32

// ---------------------------------------------------------------------------
// Probe: decide whether edge_index is int64 or int32 (device-side, graph-safe).
// int64 with values < 2^31 => every odd 32-bit word is 0.
__global__ void k_probe(const unsigned* __restrict__ ei_raw, int e) {
    __shared__ int odd_nonzero;
    if (threadIdx.x == 0) odd_nonzero = 0;
    __syncthreads();
    int i = threadIdx.x;                   // 0..127
    int words = 2 * e;                     // words if int32; int64 has 4*e but >= this
    if (2 * i + 1 < words) {
        if (ei_raw[2 * i + 1] != 0u) odd_nonzero = 1;
    }
    __syncthreads();
    if (threadIdx.x == 0) g_i64 = odd_nonzero ? 0 : 1;
}

__device__ __forceinline__ int get_idx(const void* __restrict__ ei, size_t pos) {
    if (g_i64) return (int)(reinterpret_cast<const long long*>(ei)[pos]);
    return reinterpret_cast<const int*>(ei)[pos];
}

// ---------------------------------------------------------------------------
__global__ void k_init(int n) {
    int i = blockIdx.x * blockDim.x + threadIdx.x;
    if (i >= n) return;
    g_deg[i] = 1.0f;                       // self-loop contributes 1
    g_aggx[2 * i] = 0.0f;
    g_aggx[2 * i + 1] = 0.0f;
    float4 z = make_float4(0.f, 0.f, 0.f, 0.f);
    float4* p = reinterpret_cast<float4*>(g_agg2 + (size_t)i * 32);
#pragma unroll
    for (int k = 0; k < 8; k++) p[k] = z;
}

__global__ void k_deg(const void* __restrict__ ei, int e) {
    int i = blockIdx.x * blockDim.x + threadIdx.x;
    if (i >= e) return;
    int c = get_idx(ei, (size_t)e + i);
    atomicAdd(&g_deg[c], 1.0f);
}

__global__ void k_dinv(int n) {
    int i = blockIdx.x * blockDim.x + threadIdx.x;
    if (i >= n) return;
    g_dinv[i] = rsqrtf(g_deg[i]);
}

// layer-1 aggregation on RAW x (2-dim): aggx[c] += norm * x[r]
__global__ void k_aggx(const void* __restrict__ ei,
                       const float* __restrict__ x, int e) {
    int i = blockIdx.x * blockDim.x + threadIdx.x;
    if (i >= e) return;
    int r = get_idx(ei, i);
    int c = get_idx(ei, (size_t)e + i);
    float nrm = g_dinv[r] * g_dinv[c];
    float2 xv = reinterpret_cast<const float2*>(x)[r];
    atomicAdd(&g_aggx[2 * (size_t)c], xv.x * nrm);
    atomicAdd(&g_aggx[2 * (size_t)c + 1], xv.y * nrm);
}

// per node: h1 = relu((aggx + dinv^2 * x) @ W1 + b1);  h2pre = h1 @ W2
__global__ void k_node1(const float* __restrict__ x,
                        const float* __restrict__ W1,  // [2,64]
                        const float* __restrict__ b1,  // [64]
                        const float* __restrict__ W2,  // [64,32]
                        int n) {
    __shared__ float sW1[128];
    __shared__ float sb1[64];
    __shared__ float sW2[2048];
    int t = threadIdx.x;
    for (int i = t; i < 128; i += blockDim.x) sW1[i] = W1[i];
    for (int i = t; i < 64; i += blockDim.x) sb1[i] = b1[i];
    for (int i = t; i < 2048; i += blockDim.x) sW2[i] = W2[i];
    __syncthreads();

    int nn = blockIdx.x * blockDim.x + t;
    if (nn >= n) return;
    float di = g_dinv[nn];
    float d2 = di * di;
    float2 xv = reinterpret_cast<const float2*>(x)[nn];
    float v0 = g_aggx[2 * (size_t)nn] + d2 * xv.x;
    float v1 = g_aggx[2 * (size_t)nn + 1] + d2 * xv.y;

    float acc[32];
#pragma unroll
    for (int k = 0; k < 32; k++) acc[k] = 0.0f;

#pragma unroll 4
    for (int j = 0; j < 64; j++) {
        float h = fmaxf(fmaf(v0, sW1[j], fmaf(v1, sW1[64 + j], sb1[j])), 0.0f);
#pragma unroll
        for (int k = 0; k < 32; k++) acc[k] = fmaf(h, sW2[j * 32 + k], acc[k]);
    }

    float4* o = reinterpret_cast<float4*>(g_h2pre + (size_t)nn * 32);
#pragma unroll
    for (int k = 0; k < 8; k++)
        o[k] = make_float4(acc[4 * k], acc[4 * k + 1], acc[4 * k + 2], acc[4 * k + 3]);
}

// layer-2 aggregation: 8 threads per edge, each a float4 slice.
__global__ void k_agg2(const void* __restrict__ ei, int e) {
    unsigned g = blockIdx.x * blockDim.x + threadIdx.x;
    int i = (int)(g >> 3);
    int p = (int)(g & 7u);
    if (i >= e) return;
    int r = get_idx(ei, i);
    int c = get_idx(ei, (size_t)e + i);
    float nrm = g_dinv[r] * g_dinv[c];
    float4 v = reinterpret_cast<const float4*>(g_h2pre + (size_t)r * 32)[p];
    float4* dst = reinterpret_cast<float4*>(g_agg2 + (size_t)c * 32 + 4 * p);
    atomicAdd(dst, make_float4(v.x * nrm, v.y * nrm, v.z * nrm, v.w * nrm));
}

// per node: h = relu(agg2 + dinv^2*h2pre + b2);  a = h@mW1[0:32], b = h@mW1[32:64]
__global__ void k_node2(const float* __restrict__ mW1,  // [65,16]
                        const float* __restrict__ b2,   // [32]
                        int n) {
    __shared__ float sA[512];
    __shared__ float sB[512];
    __shared__ float sb2[32];
    int t = threadIdx.x;
    for (int i = t; i < 512; i += blockDim.x) { sA[i] = mW1[i]; sB[i] = mW1[512 + i]; }
    for (int i = t; i < 32; i += blockDim.x) sb2[i] = b2[i];
    __syncthreads();

    int nn = blockIdx.x * blockDim.x + t;
    if (nn >= n) return;
    float di = g_dinv[nn];
    float d2 = di * di;

    const float4* pa = reinterpret_cast<const float4*>(g_agg2 + (size_t)nn * 32);
    const float4* ph = reinterpret_cast<const float4*>(g_h2pre + (size_t)nn * 32);

    float acca[16], accb[16];
#pragma unroll
    for (int i = 0; i < 16; i++) { acca[i] = 0.0f; accb[i] = 0.0f; }

#pragma unroll
    for (int q = 0; q < 8; q++) {
        float4 av = pa[q];
        float4 hv = ph[q];
        float hk[4];
        hk[0] = fmaxf(fmaf(d2, hv.x, av.x) + sb2[4 * q + 0], 0.0f);
        hk[1] = fmaxf(fmaf(d2, hv.y, av.y) + sb2[4 * q + 1], 0.0f);
        hk[2] = fmaxf(fmaf(d2, hv.z, av.z) + sb2[4 * q + 2], 0.0f);
        hk[3] = fmaxf(fmaf(d2, hv.w, av.w) + sb2[4 * q + 3], 0.0f);
#pragma unroll
        for (int s = 0; s < 4; s++) {
            int k = 4 * q + s;
#pragma unroll
            for (int i = 0; i < 16; i++) {
                acca[i] = fmaf(hk[s], sA[k * 16 + i], acca[i]);
                accb[i] = fmaf(hk[s], sB[k * 16 + i], accb[i]);
            }
        }
    }

    float4* oa = reinterpret_cast<float4*>(g_na + (size_t)nn * 16);
    float4* ob = reinterpret_cast<float4*>(g_nb + (size_t)nn * 16);
#pragma unroll
    for (int q = 0; q < 4; q++) {
        oa[q] = make_float4(acca[4 * q], acca[4 * q + 1], acca[4 * q + 2], acca[4 * q + 3]);
        ob[q] = make_float4(accb[4 * q], accb[4 * q + 1], accb[4 * q + 2], accb[4 * q + 3]);
    }
}

// per edge: hid = relu(a[row] + b[col] + attr*mW1[64] + mb1); out = sigmoid(hid@mW2 + mb2)
__global__ void k_edge(const void* __restrict__ ei,
                       const float* __restrict__ ea,
                       const float* __restrict__ mW1,
                       const float* __restrict__ mb1,
                       const float* __restrict__ mW2,
                       const float* __restrict__ mb2,
                       float* __restrict__ out, int e) {
    __shared__ float sw64[16], smb1[16], smw2[16];
    __shared__ float smb2;
    int t = threadIdx.x;
    if (t < 16) {
        sw64[t] = mW1[64 * 16 + t];
        smb1[t] = mb1[t];
        smw2[t] = mW2[t];
    }
    if (t == 0) smb2 = mb2[0];
    __syncthreads();

    int i = blockIdx.x * blockDim.x + t;
    if (i >= e) return;
    int r = get_idx(ei, i);
    int c = get_idx(ei, (size_t)e + i);
    float attr = ea[i];

    const float4* pa = reinterpret_cast<const float4*>(g_na + (size_t)r * 16);
    const float4* pb = reinterpret_cast<const float4*>(g_nb + (size_t)c * 16);

    float s = 0.0f;
#pragma unroll
    for (int q = 0; q < 4; q++) {
        float4 av = pa[q];
        float4 bv = pb[q];
        float h;
        h = fmaxf(av.x + bv.x + fmaf(attr, sw64[4 * q + 0], smb1[4 * q + 0]), 0.0f);
        s = fmaf(h, smw2[4 * q + 0], s);
        h = fmaxf(av.y + bv.y + fmaf(attr, sw64[4 * q + 1], smb1[4 * q + 1]), 0.0f);
        s = fmaf(h, smw2[4 * q + 1], s);
        h = fmaxf(av.z + bv.z + fmaf(attr, sw64[4 * q + 2], smb1[4 * q + 2]), 0.0f);
        s = fmaf(h, smw2[4 * q + 2], s);
        h = fmaxf(av.w + bv.w + fmaf(attr, sw64[4 * q + 3], smb1[4 * q + 3]), 0.0f);
        s = fmaf(h, smw2[4 * q + 3], s);
    }
    float z = s + smb2;
    out[i] = 1.0f / (1.0f + __expf(-z));
}

// ---------------------------------------------------------------------------
extern "C" void kernel_launch(void* const* d_in, const int* in_sizes, int n_in,
                              void* d_out, int out_size) {
    const float* x = (const float*)d_in[0];
    const void* ei = d_in[1];
    const float* ea = (const float*)d_in[2];

    // num_nodes may appear as a scalar input at index 3; detect by W1's count.
    int base = (in_sizes[3] == 128) ? 3 : 4;
    const float* W1 = (const float*)d_in[base + 0];
    const float* b1 = (const float*)d_in[base + 1];
    const float* W2 = (const float*)d_in[base + 2];
    const float* b2 = (const float*)d_in[base + 3];
    const float* mW1 = (const float*)d_in[base + 4];
    const float* mb1 = (const float*)d_in[base + 5];
    const float* mW2 = (const float*)d_in[base + 6];
    const float* mb2 = (const float*)d_in[base + 7];

    int n = in_sizes[0] / 2;       // x is [N, 2]
    int e = in_sizes[1] / 2;       // edge_index is [2, E] (element count dtype-independent)
    float* out = (float*)d_out;

    const int B = 256;
    int gn = (n + B - 1) / B;
    int ge = (e + B - 1) / B;
    unsigned ge8 = (unsigned)(((long long)e * 8 + B - 1) / B);

    k_probe<<<1, 128>>>((const unsigned*)ei, e);
    k_init<<<gn, B>>>(n);
    k_deg<<<ge, B>>>(ei, e);
    k_dinv<<<gn, B>>>(n);
    k_aggx<<<ge, B>>>(ei, x, e);
    k_node1<<<gn, B>>>(x, W1, b1, W2, n);
    k_agg2<<<ge8, B>>>(ei, e);
    k_node2<<<gn, B>>>(mW1, b2, n);
    k_edge<<<ge, B>>>(ei, ea, mW1, mb1, mW2, mb2, out, e);
}

// round 4
// speedup vs baseline: 1.1035x; 1.1035x over previous
#include <cuda_runtime.h>
#include <math.h>

#define NMAX 100000
#define EMAX 1600000

// Scratch (device globals — no allocation allowed in kernel_launch)
__device__ __align__(16) float g_deg[NMAX];
__device__ __align__(16) float g_dinv[NMAX];
__device__ __align__(16) float g_xn[NMAX * 2];      // dinv[n] * x[n]
__device__ __align__(16) float g_aggx[NMAX * 2];    // sum over in-edges of xn[r]
__device__ __align__(16) float g_h2n[NMAX * 32];    // dinv[n] * (h1 @ W2)
__device__ __align__(16) float g_agg2[NMAX * 32];   // sum over in-edges of h2n[r]
__device__ __align__(16) float g_na[NMAX * 16];     // h @ mW1[0:32]
__device__ __align__(16) float g_nb[NMAX * 16];     // h @ mW1[32:64]
__device__ __align__(16) int2  g_edge[EMAX];        // decoded (row, col)
__device__ int g_i64;

// ---------------------------------------------------------------------------
// init node scratch; block 0 also probes edge_index dtype.
// int64 with values < 2^31 => every odd 32-bit word is 0.
__global__ void k_init(const unsigned* __restrict__ ei_raw, int e, int n) {
    if (blockIdx.x == 0) {
        __shared__ int odd_nonzero;
        if (threadIdx.x == 0) odd_nonzero = 0;
        __syncthreads();
        int i = threadIdx.x;
        if (2 * i + 1 < 2 * e) {
            if (ei_raw[2 * i + 1] != 0u) odd_nonzero = 1;
        }
        __syncthreads();
        if (threadIdx.x == 0) g_i64 = odd_nonzero ? 0 : 1;
    }
    int i = blockIdx.x * blockDim.x + threadIdx.x;
    if (i >= n) return;
    g_deg[i] = 1.0f;                       // self-loop
    reinterpret_cast<float2*>(g_aggx)[i] = make_float2(0.f, 0.f);
    float4 z = make_float4(0.f, 0.f, 0.f, 0.f);
    float4* p = reinterpret_cast<float4*>(g_agg2 + (size_t)i * 32);
#pragma unroll
    for (int k = 0; k < 8; k++) p[k] = z;
}

// decode edge_index -> int2 once; accumulate degree
__global__ void k_prep(const void* __restrict__ ei, int e) {
    int i = blockIdx.x * blockDim.x + threadIdx.x;
    if (i >= e) return;
    int r, c;
    if (g_i64) {
        r = (int)(reinterpret_cast<const long long*>(ei)[i]);
        c = (int)(reinterpret_cast<const long long*>(ei)[(size_t)e + i]);
    } else {
        r = reinterpret_cast<const int*>(ei)[i];
        c = reinterpret_cast<const int*>(ei)[(size_t)e + i];
    }
    g_edge[i] = make_int2(r, c);
    atomicAdd(&g_deg[c], 1.0f);
}

// dinv = deg^-1/2 ; xn = dinv * x
__global__ void k_dinv(const float* __restrict__ x, int n) {
    int i = blockIdx.x * blockDim.x + threadIdx.x;
    if (i >= n) return;
    float di = rsqrtf(g_deg[i]);
    g_dinv[i] = di;
    float2 xv = reinterpret_cast<const float2*>(x)[i];
    reinterpret_cast<float2*>(g_xn)[i] = make_float2(di * xv.x, di * xv.y);
}

// layer-1 aggregation: aggx[c] += xn[r]   (norm factored into node kernels)
__global__ void k_aggx(int e) {
    int i = blockIdx.x * blockDim.x + threadIdx.x;
    if (i >= e) return;
    int2 eg = g_edge[i];
    float2 v = reinterpret_cast<const float2*>(g_xn)[eg.x];
    atomicAdd(reinterpret_cast<float2*>(g_aggx) + eg.y, v);
}

// per node: v = dinv*(aggx + xn) ; h1 = relu(v@W1+b1) ; h2n = dinv*(h1@W2)
__global__ void k_node1(const float* __restrict__ W1,  // [2,64]
                        const float* __restrict__ b1,  // [64]
                        const float* __restrict__ W2,  // [64,32]
                        int n) {
    __shared__ float sW1[128];
    __shared__ float sb1[64];
    __shared__ float sW2[2048];
    int t = threadIdx.x;
    for (int i = t; i < 128; i += blockDim.x) sW1[i] = W1[i];
    for (int i = t; i < 64; i += blockDim.x) sb1[i] = b1[i];
    for (int i = t; i < 2048; i += blockDim.x) sW2[i] = W2[i];
    __syncthreads();

    int nn = blockIdx.x * blockDim.x + t;
    if (nn >= n) return;
    float di = g_dinv[nn];
    float2 av = reinterpret_cast<const float2*>(g_aggx)[nn];
    float2 xv = reinterpret_cast<const float2*>(g_xn)[nn];
    float v0 = di * (av.x + xv.x);   // = dinv*aggx + dinv^2*x
    float v1 = di * (av.y + xv.y);

    float acc[32];
#pragma unroll
    for (int k = 0; k < 32; k++) acc[k] = 0.0f;

#pragma unroll 4
    for (int j = 0; j < 64; j++) {
        float h = fmaxf(fmaf(v0, sW1[j], fmaf(v1, sW1[64 + j], sb1[j])), 0.0f);
#pragma unroll
        for (int k = 0; k < 32; k++) acc[k] = fmaf(h, sW2[j * 32 + k], acc[k]);
    }

    float4* o = reinterpret_cast<float4*>(g_h2n + (size_t)nn * 32);
#pragma unroll
    for (int k = 0; k < 8; k++)
        o[k] = make_float4(di * acc[4 * k], di * acc[4 * k + 1],
                           di * acc[4 * k + 2], di * acc[4 * k + 3]);
}

// layer-2 aggregation: 8 threads/edge, pure gather + RED (no arithmetic)
__global__ void k_agg2(int e) {
    unsigned g = blockIdx.x * blockDim.x + threadIdx.x;
    int i = (int)(g >> 3);
    int p = (int)(g & 7u);
    if (i >= e) return;
    int2 eg = g_edge[i];
    float4 v = reinterpret_cast<const float4*>(g_h2n + (size_t)eg.x * 32)[p];
    atomicAdd(reinterpret_cast<float4*>(g_agg2 + (size_t)eg.y * 32) + p, v);
}

// per node: h = relu(dinv*(agg2 + h2n) + b2) ; a = h@mW1[0:32], b = h@mW1[32:64]
__global__ void k_node2(const float* __restrict__ mW1,  // [65,16]
                        const float* __restrict__ b2,   // [32]
                        int n) {
    __shared__ float sA[512];
    __shared__ float sB[512];
    __shared__ float sb2[32];
    int t = threadIdx.x;
    for (int i = t; i < 512; i += blockDim.x) { sA[i] = mW1[i]; sB[i] = mW1[512 + i]; }
    for (int i = t; i < 32; i += blockDim.x) sb2[i] = b2[i];
    __syncthreads();

    int nn = blockIdx.x * blockDim.x + t;
    if (nn >= n) return;
    float di = g_dinv[nn];

    const float4* pa = reinterpret_cast<const float4*>(g_agg2 + (size_t)nn * 32);
    const float4* ph = reinterpret_cast<const float4*>(g_h2n + (size_t)nn * 32);

    float acca[16], accb[16];
#pragma unroll
    for (int i = 0; i < 16; i++) { acca[i] = 0.0f; accb[i] = 0.0f; }

#pragma unroll
    for (int q = 0; q < 8; q++) {
        float4 av = pa[q];
        float4 hv = ph[q];
        float hk[4];
        hk[0] = fmaxf(fmaf(di, av.x + hv.x, sb2[4 * q + 0]), 0.0f);
        hk[1] = fmaxf(fmaf(di, av.y + hv.y, sb2[4 * q + 1]), 0.0f);
        hk[2] = fmaxf(fmaf(di, av.z + hv.z, sb2[4 * q + 2]), 0.0f);
        hk[3] = fmaxf(fmaf(di, av.w + hv.w, sb2[4 * q + 3]), 0.0f);
#pragma unroll
        for (int s = 0; s < 4; s++) {
            int k = 4 * q + s;
#pragma unroll
            for (int i = 0; i < 16; i++) {
                acca[i] = fmaf(hk[s], sA[k * 16 + i], acca[i]);
                accb[i] = fmaf(hk[s], sB[k * 16 + i], accb[i]);
            }
        }
    }

    float4* oa = reinterpret_cast<float4*>(g_na + (size_t)nn * 16);
    float4* ob = reinterpret_cast<float4*>(g_nb + (size_t)nn * 16);
#pragma unroll
    for (int q = 0; q < 4; q++) {
        oa[q] = make_float4(acca[4 * q], acca[4 * q + 1], acca[4 * q + 2], acca[4 * q + 3]);
        ob[q] = make_float4(accb[4 * q], accb[4 * q + 1], accb[4 * q + 2], accb[4 * q + 3]);
    }
}

// per edge: hid = relu(na[r] + nb[c] + attr*mW1[64] + mb1); out = sigmoid(hid@mW2 + mb2)
__global__ void k_edge(const float* __restrict__ ea,
                       const float* __restrict__ mW1,
                       const float* __restrict__ mb1,
                       const float* __restrict__ mW2,
                       const float* __restrict__ mb2,
                       float* __restrict__ out, int e) {
    __shared__ float sw64[16], smb1[16], smw2[16];
    __shared__ float smb2;
    int t = threadIdx.x;
    if (t < 16) {
        sw64[t] = mW1[64 * 16 + t];
        smb1[t] = mb1[t];
        smw2[t] = mW2[t];
    }
    if (t == 0) smb2 = mb2[0];
    __syncthreads();

    int i = blockIdx.x * blockDim.x + t;
    if (i >= e) return;
    int2 eg = g_edge[i];
    float attr = ea[i];

    const float4* pa = reinterpret_cast<const float4*>(g_na + (size_t)eg.x * 16);
    const float4* pb = reinterpret_cast<const float4*>(g_nb + (size_t)eg.y * 16);

    float s = 0.0f;
#pragma unroll
    for (int q = 0; q < 4; q++) {
        float4 av = pa[q];
        float4 bv = pb[q];
        float h;
        h = fmaxf(av.x + bv.x + fmaf(attr, sw64[4 * q + 0], smb1[4 * q + 0]), 0.0f);
        s = fmaf(h, smw2[4 * q + 0], s);
        h = fmaxf(av.y + bv.y + fmaf(attr, sw64[4 * q + 1], smb1[4 * q + 1]), 0.0f);
        s = fmaf(h, smw2[4 * q + 1], s);
        h = fmaxf(av.z + bv.z + fmaf(attr, sw64[4 * q + 2], smb1[4 * q + 2]), 0.0f);
        s = fmaf(h, smw2[4 * q + 2], s);
        h = fmaxf(av.w + bv.w + fmaf(attr, sw64[4 * q + 3], smb1[4 * q + 3]), 0.0f);
        s = fmaf(h, smw2[4 * q + 3], s);
    }
    float z = s + smb2;
    out[i] = 1.0f / (1.0f + __expf(-z));
}

// ---------------------------------------------------------------------------
extern "C" void kernel_launch(void* const* d_in, const int* in_sizes, int n_in,
                              void* d_out, int out_size) {
    const void* ei = d_in[1];
    const float* ea = (const float*)d_in[2];
    const float* x = (const float*)d_in[0];

    int base = (in_sizes[3] == 128) ? 3 : 4;
    const float* W1 = (const float*)d_in[base + 0];
    const float* b1 = (const float*)d_in[base + 1];
    const float* W2 = (const float*)d_in[base + 2];
    const float* b2 = (const float*)d_in[base + 3];
    const float* mW1 = (const float*)d_in[base + 4];
    const float* mb1 = (const float*)d_in[base + 5];
    const float* mW2 = (const float*)d_in[base + 6];
    const float* mb2 = (const float*)d_in[base + 7];

    int n = in_sizes[0] / 2;
    int e = in_sizes[1] / 2;
    float* out = (float*)d_out;

    const int B = 256;
    int gn = (n + B - 1) / B;
    int ge = (e + B - 1) / B;
    unsigned ge8 = (unsigned)(((long long)e * 8 + B - 1) / B);

    k_init<<<gn, B>>>((const unsigned*)ei, e, n);
    k_prep<<<ge, B>>>(ei, e);
    k_dinv<<<gn, B>>>(x, n);
    k_aggx<<<ge, B>>>(e);
    k_node1<<<gn, B>>>(W1, b1, W2, n);
    k_agg2<<<ge8, B>>>(e);
    k_node2<<<gn, B>>>(mW1, b2, n);
    k_edge<<<ge, B>>>(ea, mW1, mb1, mW2, mb2, out, e);
}

// round 5
// speedup vs baseline: 1.2403x; 1.1239x over previous
#include <cuda_runtime.h>
#include <cuda_fp16.h>
#include <math.h>

#define NMAX 100000
#define EMAX 1600000

// Scratch (device globals — no allocation allowed in kernel_launch)
__device__ __align__(16) float  g_deg[NMAX];
__device__ __align__(16) float  g_dinv[NMAX];
__device__ __align__(16) float  g_xn[NMAX * 2];      // dinv[n] * x[n]
__device__ __align__(16) float  g_aggx[NMAX * 2];    // sum over in-edges of xn[r]
__device__ __align__(16) __half g_h2n[NMAX * 32];    // fp16: dinv[n] * (h1 @ W2)
__device__ __align__(16) float  g_agg2[NMAX * 32];   // f32 accumulator
__device__ __align__(16) __half g_na[NMAX * 16];     // fp16: h @ mW1[0:32]
__device__ __align__(16) __half g_nb[NMAX * 16];     // fp16: h @ mW1[32:64]
__device__ __align__(16) int2   g_edge[EMAX];        // decoded (row, col)
__device__ int g_i64;

// ---------------------------------------------------------------------------
// init node scratch; block 0 also probes edge_index dtype.
__global__ void k_init(const unsigned* __restrict__ ei_raw, int e, int n) {
    if (blockIdx.x == 0) {
        __shared__ int odd_nonzero;
        if (threadIdx.x == 0) odd_nonzero = 0;
        __syncthreads();
        int i = threadIdx.x;
        if (2 * i + 1 < 2 * e) {
            if (ei_raw[2 * i + 1] != 0u) odd_nonzero = 1;
        }
        __syncthreads();
        if (threadIdx.x == 0) g_i64 = odd_nonzero ? 0 : 1;
    }
    int i = blockIdx.x * blockDim.x + threadIdx.x;
    if (i >= n) return;
    g_deg[i] = 1.0f;                       // self-loop
    reinterpret_cast<float2*>(g_aggx)[i] = make_float2(0.f, 0.f);
    float4 z = make_float4(0.f, 0.f, 0.f, 0.f);
    float4* p = reinterpret_cast<float4*>(g_agg2 + (size_t)i * 32);
#pragma unroll
    for (int k = 0; k < 8; k++) p[k] = z;
}

// decode edge_index -> int2 once; accumulate degree
__global__ void k_prep(const void* __restrict__ ei, int e) {
    int i = blockIdx.x * blockDim.x + threadIdx.x;
    if (i >= e) return;
    int r, c;
    if (g_i64) {
        r = (int)(reinterpret_cast<const long long*>(ei)[i]);
        c = (int)(reinterpret_cast<const long long*>(ei)[(size_t)e + i]);
    } else {
        r = reinterpret_cast<const int*>(ei)[i];
        c = reinterpret_cast<const int*>(ei)[(size_t)e + i];
    }
    g_edge[i] = make_int2(r, c);
    atomicAdd(&g_deg[c], 1.0f);
}

// dinv = deg^-1/2 ; xn = dinv * x
__global__ void k_dinv(const float* __restrict__ x, int n) {
    int i = blockIdx.x * blockDim.x + threadIdx.x;
    if (i >= n) return;
    float di = rsqrtf(g_deg[i]);
    g_dinv[i] = di;
    float2 xv = reinterpret_cast<const float2*>(x)[i];
    reinterpret_cast<float2*>(g_xn)[i] = make_float2(di * xv.x, di * xv.y);
}

// layer-1 aggregation: aggx[c] += xn[r]
__global__ void k_aggx(int e) {
    int i = blockIdx.x * blockDim.x + threadIdx.x;
    if (i >= e) return;
    int2 eg = g_edge[i];
    float2 v = reinterpret_cast<const float2*>(g_xn)[eg.x];
    atomicAdd(reinterpret_cast<float2*>(g_aggx) + eg.y, v);
}

// per node: v = dinv*(aggx + xn) ; h1 = relu(v@W1+b1) ; h2n = fp16(dinv*(h1@W2))
__global__ void k_node1(const float* __restrict__ W1,  // [2,64]
                        const float* __restrict__ b1,  // [64]
                        const float* __restrict__ W2,  // [64,32]
                        int n) {
    __shared__ float sW1[128];
    __shared__ float sb1[64];
    __shared__ float sW2[2048];
    int t = threadIdx.x;
    for (int i = t; i < 128; i += blockDim.x) sW1[i] = W1[i];
    for (int i = t; i < 64; i += blockDim.x) sb1[i] = b1[i];
    for (int i = t; i < 2048; i += blockDim.x) sW2[i] = W2[i];
    __syncthreads();

    int nn = blockIdx.x * blockDim.x + t;
    if (nn >= n) return;
    float di = g_dinv[nn];
    float2 av = reinterpret_cast<const float2*>(g_aggx)[nn];
    float2 xv = reinterpret_cast<const float2*>(g_xn)[nn];
    float v0 = di * (av.x + xv.x);
    float v1 = di * (av.y + xv.y);

    float acc[32];
#pragma unroll
    for (int k = 0; k < 32; k++) acc[k] = 0.0f;

#pragma unroll 4
    for (int j = 0; j < 64; j++) {
        float h = fmaxf(fmaf(v0, sW1[j], fmaf(v1, sW1[64 + j], sb1[j])), 0.0f);
#pragma unroll
        for (int k = 0; k < 32; k++) acc[k] = fmaf(h, sW2[j * 32 + k], acc[k]);
    }

    // pack 32 floats -> 16 half2 -> 4 uint4
    __half2 hp[16];
#pragma unroll
    for (int k = 0; k < 16; k++)
        hp[k] = __floats2half2_rn(di * acc[2 * k], di * acc[2 * k + 1]);
    uint4* o = reinterpret_cast<uint4*>(g_h2n + (size_t)nn * 32);
    const uint4* src = reinterpret_cast<const uint4*>(hp);
#pragma unroll
    for (int k = 0; k < 4; k++) o[k] = src[k];
}

// layer-2 aggregation: 4 threads/edge; fp16 gather (16B each), f32 v4 RED
__global__ void k_agg2(int e) {
    unsigned g = blockIdx.x * blockDim.x + threadIdx.x;
    int i = (int)(g >> 2);
    int p = (int)(g & 3u);
    if (i >= e) return;
    int2 eg = g_edge[i];
    uint4 raw = reinterpret_cast<const uint4*>(g_h2n + (size_t)eg.x * 32)[p];
    const __half2* h = reinterpret_cast<const __half2*>(&raw);
    float2 f0 = __half22float2(h[0]);
    float2 f1 = __half22float2(h[1]);
    float2 f2 = __half22float2(h[2]);
    float2 f3 = __half22float2(h[3]);
    float4* dst = reinterpret_cast<float4*>(g_agg2 + (size_t)eg.y * 32 + 8 * p);
    atomicAdd(dst,     make_float4(f0.x, f0.y, f1.x, f1.y));
    atomicAdd(dst + 1, make_float4(f2.x, f2.y, f3.x, f3.y));
}

// per node: h = relu(dinv*(agg2 + h2n) + b2) ; na = fp16(h@A), nb = fp16(h@B)
__global__ void k_node2(const float* __restrict__ mW1,  // [65,16]
                        const float* __restrict__ b2,   // [32]
                        int n) {
    __shared__ float sA[512];
    __shared__ float sB[512];
    __shared__ float sb2[32];
    int t = threadIdx.x;
    for (int i = t; i < 512; i += blockDim.x) { sA[i] = mW1[i]; sB[i] = mW1[512 + i]; }
    for (int i = t; i < 32; i += blockDim.x) sb2[i] = b2[i];
    __syncthreads();

    int nn = blockIdx.x * blockDim.x + t;
    if (nn >= n) return;
    float di = g_dinv[nn];

    const float4* pa = reinterpret_cast<const float4*>(g_agg2 + (size_t)nn * 32);
    const uint4* phr = reinterpret_cast<const uint4*>(g_h2n + (size_t)nn * 32);

    float acca[16], accb[16];
#pragma unroll
    for (int i = 0; i < 16; i++) { acca[i] = 0.0f; accb[i] = 0.0f; }

#pragma unroll
    for (int q = 0; q < 4; q++) {               // q: uint4 chunk = 8 values
        uint4 raw = phr[q];
        const __half2* hh = reinterpret_cast<const __half2*>(&raw);
        float4 av0 = pa[2 * q];
        float4 av1 = pa[2 * q + 1];
        float hv[8];
        float2 c0 = __half22float2(hh[0]);
        float2 c1 = __half22float2(hh[1]);
        float2 c2 = __half22float2(hh[2]);
        float2 c3 = __half22float2(hh[3]);
        hv[0] = c0.x; hv[1] = c0.y; hv[2] = c1.x; hv[3] = c1.y;
        hv[4] = c2.x; hv[5] = c2.y; hv[6] = c3.x; hv[7] = c3.y;
        float avf[8] = {av0.x, av0.y, av0.z, av0.w, av1.x, av1.y, av1.z, av1.w};
        float hk[8];
#pragma unroll
        for (int s = 0; s < 8; s++)
            hk[s] = fmaxf(fmaf(di, avf[s] + hv[s], sb2[8 * q + s]), 0.0f);
#pragma unroll
        for (int s = 0; s < 8; s++) {
            int k = 8 * q + s;
#pragma unroll
            for (int i = 0; i < 16; i++) {
                acca[i] = fmaf(hk[s], sA[k * 16 + i], acca[i]);
                accb[i] = fmaf(hk[s], sB[k * 16 + i], accb[i]);
            }
        }
    }

    __half2 hpa[8], hpb[8];
#pragma unroll
    for (int k = 0; k < 8; k++) {
        hpa[k] = __floats2half2_rn(acca[2 * k], acca[2 * k + 1]);
        hpb[k] = __floats2half2_rn(accb[2 * k], accb[2 * k + 1]);
    }
    uint4* oa = reinterpret_cast<uint4*>(g_na + (size_t)nn * 16);
    uint4* ob = reinterpret_cast<uint4*>(g_nb + (size_t)nn * 16);
    const uint4* sa = reinterpret_cast<const uint4*>(hpa);
    const uint4* sb = reinterpret_cast<const uint4*>(hpb);
    oa[0] = sa[0]; oa[1] = sa[1];
    ob[0] = sb[0]; ob[1] = sb[1];
}

// per edge: hid = relu(na[r] + nb[c] + attr*mW1[64] + mb1); out = sigmoid(hid@mW2 + mb2)
__global__ void k_edge(const float* __restrict__ ea,
                       const float* __restrict__ mW1,
                       const float* __restrict__ mb1,
                       const float* __restrict__ mW2,
                       const float* __restrict__ mb2,
                       float* __restrict__ out, int e) {
    __shared__ float sw64[16], smb1[16], smw2[16];
    __shared__ float smb2;
    int t = threadIdx.x;
    if (t < 16) {
        sw64[t] = mW1[64 * 16 + t];
        smb1[t] = mb1[t];
        smw2[t] = mW2[t];
    }
    if (t == 0) smb2 = mb2[0];
    __syncthreads();

    int i = blockIdx.x * blockDim.x + t;
    if (i >= e) return;
    int2 eg = g_edge[i];
    float attr = ea[i];

    const uint4* pa = reinterpret_cast<const uint4*>(g_na + (size_t)eg.x * 16);
    const uint4* pb = reinterpret_cast<const uint4*>(g_nb + (size_t)eg.y * 16);
    uint4 ra0 = pa[0], ra1 = pa[1];
    uint4 rb0 = pb[0], rb1 = pb[1];
    const __half2* ha = reinterpret_cast<const __half2*>(&ra0);  // 4 half2 then ra1
    const __half2* hb = reinterpret_cast<const __half2*>(&rb0);

    float s = 0.0f;
#pragma unroll
    for (int q = 0; q < 4; q++) {
        float2 av = __half22float2(ha[q]);
        float2 bv = __half22float2(hb[q]);
        float h;
        h = fmaxf(av.x + bv.x + fmaf(attr, sw64[2 * q], smb1[2 * q]), 0.0f);
        s = fmaf(h, smw2[2 * q], s);
        h = fmaxf(av.y + bv.y + fmaf(attr, sw64[2 * q + 1], smb1[2 * q + 1]), 0.0f);
        s = fmaf(h, smw2[2 * q + 1], s);
    }
    const __half2* ha1 = reinterpret_cast<const __half2*>(&ra1);
    const __half2* hb1 = reinterpret_cast<const __half2*>(&rb1);
#pragma unroll
    for (int q = 0; q < 4; q++) {
        float2 av = __half22float2(ha1[q]);
        float2 bv = __half22float2(hb1[q]);
        float h;
        h = fmaxf(av.x + bv.x + fmaf(attr, sw64[8 + 2 * q], smb1[8 + 2 * q]), 0.0f);
        s = fmaf(h, smw2[8 + 2 * q], s);
        h = fmaxf(av.y + bv.y + fmaf(attr, sw64[8 + 2 * q + 1], smb1[8 + 2 * q + 1]), 0.0f);
        s = fmaf(h, smw2[8 + 2 * q + 1], s);
    }
    float z = s + smb2;
    out[i] = 1.0f / (1.0f + __expf(-z));
}

// ---------------------------------------------------------------------------
extern "C" void kernel_launch(void* const* d_in, const int* in_sizes, int n_in,
                              void* d_out, int out_size) {
    const float* x = (const float*)d_in[0];
    const void* ei = d_in[1];
    const float* ea = (const float*)d_in[2];

    int base = (in_sizes[3] == 128) ? 3 : 4;
    const float* W1 = (const float*)d_in[base + 0];
    const float* b1 = (const float*)d_in[base + 1];
    const float* W2 = (const float*)d_in[base + 2];
    const float* b2 = (const float*)d_in[base + 3];
    const float* mW1 = (const float*)d_in[base + 4];
    const float* mb1 = (const float*)d_in[base + 5];
    const float* mW2 = (const float*)d_in[base + 6];
    const float* mb2 = (const float*)d_in[base + 7];

    int n = in_sizes[0] / 2;
    int e = in_sizes[1] / 2;
    float* out = (float*)d_out;

    const int B = 256;
    int gn = (n + B - 1) / B;
    int ge = (e + B - 1) / B;
    unsigned ge4 = (unsigned)(((long long)e * 4 + B - 1) / B);

    k_init<<<gn, B>>>((const unsigned*)ei, e, n);
    k_prep<<<ge, B>>>(ei, e);
    k_dinv<<<gn, B>>>(x, n);
    k_aggx<<<ge, B>>>(e);
    k_node1<<<gn, B>>>(W1, b1, W2, n);
    k_agg2<<<ge4, B>>>(e);
    k_node2<<<gn, B>>>(mW1, b2, n);
    k_edge<<<ge, B>>>(ea, mW1, mb1, mW2, mb2, out, e);
}